// round 15
// baseline (speedup 1.0000x reference)
#include <cuda_runtime.h>
#include <cuda_fp16.h>
#include <cstdint>

#define BB 8
#define TT 512
#define HH 65
#define G4 260
#define VV 32000
#define NROW (BB*TT)          /* 4096 */
#define KB16 144              /* packed fp16 K per row: [Zhi(68)|Zlo(68)|0(8)] */

static const long long OUT_MAIN_SIZE = (long long)NROW * VV;  // 131072000

// ---------------- scratch (device globals; no allocation allowed) ----------
__device__ float g_Xg[NROW * G4];
__device__ float g_enc[NROW * HH];
__device__ float g_q[NROW * HH];
__device__ float g_son[NROW];
__device__ float g_soff[NROW];
__device__ float g_ctx[NROW * HH];
__device__ __half g_Zb[NROW * KB16];          // packed A rows (fp16)
__device__ __half g_Wb[(size_t)VV * KB16];    // packed B rows (fp16)

// ---------------- small helpers -------------------------------------------
union F2U { float2 f; unsigned long long u; };
__device__ __forceinline__ unsigned long long ffma2u(unsigned long long a,
                                                     unsigned long long b,
                                                     unsigned long long c) {
    unsigned long long d;
    asm("fma.rn.f32x2 %0, %1, %2, %3;" : "=l"(d) : "l"(a), "l"(b), "l"(c));
    return d;
}
__device__ __forceinline__ unsigned long long addx2(unsigned long long a,
                                                    unsigned long long b) {
    unsigned long long d;
    asm("add.rn.f32x2 %0, %1, %2;" : "=l"(d) : "l"(a), "l"(b));
    return d;
}
__device__ __forceinline__ float tanh_fast(float x) {
    return 1.f - __fdividef(2.f, __expf(2.f * x) + 1.f);
}
__device__ __forceinline__ uint32_t smem_u32(const void* p) {
    uint32_t a;
    asm("{ .reg .u64 t; cvta.to.shared.u64 t, %1; cvt.u32.u64 %0, t; }" : "=r"(a) : "l"(p));
    return a;
}

// fp16 2-section packers. A: [Zhi(68)|Zlo(68)|0(8)]  B: [Whi(68)|Whi(68)|0(8)]
__device__ __forceinline__ __half zb_elem(const float* zr, int k) {
    int j = (k < 68) ? k : k - 68;
    if (k >= 136 || j >= 65) return __float2half(0.f);
    float z = zr[j];
    __half hi = __float2half(z);
    if (k >= 68) return __float2half(z - __half2float(hi));
    return hi;
}
__device__ __forceinline__ __half wb_elem(const float* wr, int k) {
    int j = (k < 68) ? k : k - 68;
    if (k >= 136 || j >= 65) return __float2half(0.f);
    return __float2half(wr[j]);
}

// ---------------- warp MMA primitives (baseline PTX, works at sm_103) ------
#define LDSM4(r0, r1, r2, r3, a) \
    asm volatile("ldmatrix.sync.aligned.m8n8.x4.shared.b16 {%0,%1,%2,%3}, [%4];" \
                 : "=r"(r0), "=r"(r1), "=r"(r2), "=r"(r3) : "r"(a))

__device__ __forceinline__ void mma16816(float* c, const uint32_t* a, uint32_t b0, uint32_t b1) {
    asm volatile(
        "mma.sync.aligned.m16n8k16.row.col.f32.f16.f16.f32 "
        "{%0,%1,%2,%3},{%4,%5,%6,%7},{%8,%9},{%0,%1,%2,%3};"
        : "+f"(c[0]), "+f"(c[1]), "+f"(c[2]), "+f"(c[3])
        : "r"(a[0]), "r"(a[1]), "r"(a[2]), "r"(a[3]), "r"(b0), "r"(b1));
}
__device__ __forceinline__ void cp16(uint32_t s, const void* g) {
    asm volatile("cp.async.cg.shared.global [%0], [%1], 16;" :: "r"(s), "l"(g));
}
#define CP_COMMIT() asm volatile("cp.async.commit_group;" ::: "memory")
#define CP_WAIT0()  asm volatile("cp.async.wait_group 0;" ::: "memory")

// ---------------- embedding + x-part of LSTM gates -------------------------
__global__ void k_embed(const int* __restrict__ ids, const float* __restrict__ emb,
                        const float* __restrict__ w_ih, const float* __restrict__ b_ih,
                        const float* __restrict__ b_hh) {
    __shared__ float sw[130 * 65];
    __shared__ float er[16 * 65];
    __shared__ float bs[130];
    int row0 = blockIdx.x * 16;
    int g0   = blockIdx.y * 130;
    int tid  = threadIdx.x;
    for (int i = tid; i < 130 * 65; i += 256) sw[i] = w_ih[g0 * 65 + i];
    for (int i = tid; i < 16 * 65; i += 256) {
        int r = i / 65, k = i - r * 65;
        er[i] = emb[ids[row0 + r] * 65 + k];
    }
    if (tid < 130) bs[tid] = b_ih[g0 + tid] + b_hh[g0 + tid];
    __syncthreads();
    for (int o = tid; o < 16 * 130; o += 256) {
        int r = o / 130, g = o - r * 130;
        float acc = bs[g];
        const float* w = sw + g * 65;
        const float* x = er + r * 65;
        #pragma unroll 13
        for (int k = 0; k < 65; k++) acc = fmaf(w[k], x[k], acc);
        g_Xg[(row0 + r) * G4 + g0 + g] = acc;
    }
}

// ---------------- fused LSTM recurrence + weight pack ----------------------
// LSTM blocks: 1024 threads, Ksplit=4. Primary: thread t<1008 -> row=t>>2,
// quarter q=t&3 (16-17 MACs). Tail threads 1008..1023 (warp31 lanes 16..31):
// rows 252..259 half-split (o-gate j=57..64). Gate exchange via smem sgate.
__global__ void __launch_bounds__(1024, 1)
k_lstm_pack(const float* __restrict__ h0, const float* __restrict__ c0,
            const float* __restrict__ w_hh, const float* __restrict__ ov_w,
            float* __restrict__ outH, float* __restrict__ outC) {
    int tid = threadIdx.x;

    if (blockIdx.x >= BB) {
        // ---------------- pack path (gmem -> gmem) -------------------------
        int v0 = (blockIdx.x - BB) * 64;
        for (int o = tid; o < 64 * 72; o += 1024) {
            int r = o / 72, p = o - r * 72, k0 = 2 * p;
            const float* wr = ov_w + (size_t)(v0 + r) * 65;
            __half2 val;
            val.x = wb_elem(wr, k0);
            val.y = wb_elem(wr, k0 + 1);
            *(__half2*)(g_Wb + ((size_t)(v0 + r)) * KB16 + k0) = val;
        }
        return;
    }

    // ---------------- LSTM path -------------------------------------------
    int b = blockIdx.x;
    bool special = (tid >= 1008);
    int d = tid - 1008;
    int row, kbase;
    bool do_store;
    if (special) { row = 252 + (d >> 1); kbase = (d & 1) * 32; do_store = ((d & 1) == 0); }
    else         { row = tid >> 2;       kbase = (tid & 3) * 16; do_store = ((tid & 3) == 0); }
    int gate = row / 65;
    int j = row - gate * 65;
    bool upd = (!special) && do_store && (row < 65);   // row==j, gate==0

    __shared__ __align__(16) float hs[2][68];
    __shared__ float sgate[260];

    // weights: pairs p cover k = kbase+2p
    const float* wr = w_hh + row * 65 + kbase;
    F2U w2[17];
    #pragma unroll
    for (int i = 0; i < 8; i++) { w2[i].f.x = wr[2 * i]; w2[i].f.y = wr[2 * i + 1]; }
    if (special) {
        #pragma unroll
        for (int i = 8; i < 16; i++) { w2[i].f.x = wr[2 * i]; w2[i].f.y = wr[2 * i + 1]; }
        w2[16].f.x = (d & 1) ? w_hh[row * 65 + 64] : 0.f;
        w2[16].f.y = 0.f;
    } else {
        // pair 8 pairs with h[kbase+16, kbase+17]; only q==3 contributes (k=64)
        if ((tid & 3) == 3) { w2[8].f.x = w_hh[row * 65 + 64]; w2[8].f.y = 0.f; }
        else                { w2[8].u = 0ull; }
    }

    float c1   = (gate == 2) ? -2.885390082f : -1.442695041f;
    float amul = (gate == 2) ? 2.f : 1.f;
    float aadd = (gate == 2) ? -1.f : 0.f;

    float c = upd ? c0[b * 65 + j] : 0.f;
    if (tid < 65) hs[0][tid] = h0[b * 65 + tid];
    if (tid >= 65 && tid < 68) { hs[0][tid] = 0.f; hs[1][tid] = 0.f; }

    const float* xgp = g_Xg + (size_t)b * TT * G4 + row;
    float xg_cur = do_store ? xgp[0] : 0.f;
    __syncthreads();

    for (int t = 0; t < TT; t++) {
        float xg_next = 0.f;
        if (do_store && t + 1 < TT) xg_next = xgp[(size_t)(t + 1) * G4];

        const float* hb = hs[t & 1] + kbase;
        const ulonglong2* hp = (const ulonglong2*)hb;
        ulonglong2 p0 = hp[0], p1 = hp[1], p2 = hp[2], p3 = hp[3];
        unsigned long long p8 = *(const unsigned long long*)(hb + 16);

        F2U a0, a1, a2, a3;
        a0.f = make_float2(xg_cur, 0.f);
        a1.u = 0ull; a2.u = 0ull; a3.u = 0ull;
        a0.u = ffma2u(w2[0].u, p0.x, a0.u);
        a1.u = ffma2u(w2[1].u, p0.y, a1.u);
        a2.u = ffma2u(w2[2].u, p1.x, a2.u);
        a3.u = ffma2u(w2[3].u, p1.y, a3.u);
        a0.u = ffma2u(w2[4].u, p2.x, a0.u);
        a1.u = ffma2u(w2[5].u, p2.y, a1.u);
        a2.u = ffma2u(w2[6].u, p3.x, a2.u);
        a3.u = ffma2u(w2[7].u, p3.y, a3.u);
        a0.u = ffma2u(w2[8].u, p8, a0.u);
        if (special) {           // warp 31 only; lanes 16..31 contribute
            ulonglong2 p4 = hp[4], p5 = hp[5], p6 = hp[6], p7 = hp[7];
            unsigned long long p16 = *(const unsigned long long*)(hb + 32);
            a1.u = ffma2u(w2[9].u,  p4.y, a1.u);
            a2.u = ffma2u(w2[10].u, p5.x, a2.u);
            a3.u = ffma2u(w2[11].u, p5.y, a3.u);
            a0.u = ffma2u(w2[12].u, p6.x, a0.u);
            a1.u = ffma2u(w2[13].u, p6.y, a1.u);
            a2.u = ffma2u(w2[14].u, p7.x, a2.u);
            a3.u = ffma2u(w2[15].u, p7.y, a3.u);
            a0.u = ffma2u(w2[16].u, p16, a0.u);
        }
        F2U s;
        s.u = addx2(addx2(a0.u, a1.u), addx2(a2.u, a3.u));
        float part = s.f.x + s.f.y;
        float s1 = part + __shfl_xor_sync(0xffffffffu, part, 1);
        float s2 = s1 + __shfl_xor_sync(0xffffffffu, s1, 2);
        float sum = special ? s1 : s2;

        float ex;
        asm("ex2.approx.f32 %0, %1;" : "=f"(ex) : "f"(c1 * sum));
        float sg = __fdividef(1.f, 1.f + ex);
        float av = fmaf(amul, sg, aadd);

        if (do_store) sgate[row] = av;
        __syncthreads();

        if (upd) {
            float fv = sgate[65 + j];
            float gg = sgate[130 + j];
            float ov = sgate[195 + j];
            c = fv * c + av * gg;                 // av = sigmoid(i) here
            float h = ov * tanh_fast(c);
            hs[(t + 1) & 1][j] = h;
            g_enc[(size_t)(b * TT + t) * HH + j] = h;
        }
        __syncthreads();
        xg_cur = xg_next;
    }
    if (upd) { outH[b * 65 + j] = hs[TT & 1][j]; outC[b * 65 + j] = c; }
}

// ---------------- queries + attention scores -------------------------------
__global__ void k_keys(const float* __restrict__ u_w, const float* __restrict__ u_b,
                       const float* __restrict__ w_w, const float* __restrict__ w_b,
                       const float* __restrict__ v_w, const float* __restrict__ v_b) {
    __shared__ float swu[65 * 65];
    __shared__ float sww[65 * 65];
    __shared__ float senc[16 * 65];
    __shared__ float sq[16 * 65];
    __shared__ float skq[16 * 65];
    __shared__ float sv[65];
    int row0 = blockIdx.x * 16, tid = threadIdx.x;
    for (int i = tid; i < 65 * 65; i += 256) { swu[i] = u_w[i]; sww[i] = w_w[i]; }
    for (int i = tid; i < 16 * 65; i += 256) senc[i] = g_enc[row0 * 65 + i];
    if (tid < 65) sv[tid] = v_w[tid];
    __syncthreads();
    for (int o = tid; o < 16 * 65; o += 256) {
        int r = o / 65, j = o - r * 65;
        float aq = u_b[j], ak = w_b[j];
        const float* wu = swu + j * 65;
        const float* wk = sww + j * 65;
        const float* x  = senc + r * 65;
        #pragma unroll 13
        for (int k = 0; k < 65; k++) {
            aq = fmaf(wu[k], x[k], aq);
            ak = fmaf(wk[k], x[k], ak);
        }
        sq[o] = aq;
        skq[o] = ak;
        g_q[(row0 + r) * 65 + j] = aq;
    }
    __syncthreads();
    int r = tid >> 4, l = tid & 15;
    float sn = 0.f, sf = 0.f;
    for (int j = l; j < 65; j += 16) {
        float kq = skq[r * 65 + j];
        float qv = sq[r * 65 + j];
        float vj = sv[j];
        sn = fmaf(vj, tanh_fast(kq + qv), sn);
        sf = fmaf(vj, tanh_fast(kq), sf);
    }
    #pragma unroll
    for (int off = 8; off; off >>= 1) {
        sn += __shfl_down_sync(0xffffffffu, sn, off, 16);
        sf += __shfl_down_sync(0xffffffffu, sf, off, 16);
    }
    if (l == 0) {
        g_son[row0 + r]  = sn + v_b[0];
        g_soff[row0 + r] = sf + v_b[0];
    }
}

// ---------------- attention via prefix sums (one block per batch) ----------
__global__ void __launch_bounds__(288, 1) k_attn() {
    int b = blockIdx.x, tid = threadIdx.x;
    __shared__ float eon[512], eoff[512], con[512], coff[512], invD[512];
    __shared__ float ssn[4][72], ssf[4][72];
    __shared__ float offon[16], offoff[16];
    __shared__ float red[288];
    __shared__ float Msh, totoff_sh;
    const float* son  = g_son  + b * TT;
    const float* soff = g_soff + b * TT;

    float m = -1e30f;
    for (int j = tid; j < TT; j += 288) m = fmaxf(m, fmaxf(son[j], soff[j]));
    red[tid] = m;
    __syncthreads();
    if (tid == 0) { float mm = red[0]; for (int i = 1; i < 288; i++) mm = fmaxf(mm, red[i]); Msh = mm; }
    __syncthreads();
    float M = Msh;
    for (int j = tid; j < TT; j += 288) { eon[j] = __expf(son[j] - M); eoff[j] = __expf(soff[j] - M); }
    __syncthreads();
    if (tid < 16) {
        float s = 0; int base = tid * 32;
        for (int k = 0; k < 32; k++) { s += eon[base + k]; con[base + k] = s; }
    } else if (tid < 32) {
        float s = 0; int base = (tid - 16) * 32;
        for (int k = 0; k < 32; k++) { s += eoff[base + k]; coff[base + k] = s; }
    }
    __syncthreads();
    if (tid == 0) { float s = 0; for (int c = 0; c < 16; c++) { offon[c] = s;  s += con[c * 32 + 31]; } }
    if (tid == 1) { float s = 0; for (int c = 0; c < 16; c++) { offoff[c] = s; s += coff[c * 32 + 31]; } }
    __syncthreads();
    for (int j = tid; j < TT; j += 288) { con[j] += offon[j >> 5]; coff[j] += offoff[j >> 5]; }
    __syncthreads();
    if (tid == 0) totoff_sh = coff[511];
    __syncthreads();
    float totoff = totoff_sh;
    for (int i = tid; i < TT; i += 288) invD[i] = 1.f / (con[i] + totoff - coff[i]);
    __syncthreads();

    int c = tid / 72, h = tid - c * 72;
    const float* qb = g_q + b * TT * 65;
    if (h < 65) {
        int j0 = c * 128;
        float sn = 0, sf = 0;
        for (int j = j0; j < j0 + 128; j++) {
            float qv = qb[j * 65 + h];
            sn = fmaf(eon[j], qv, sn);
            sf = fmaf(eoff[j], qv, sf);
        }
        ssn[c][h] = sn; ssf[c][h] = sf;
    }
    __syncthreads();
    if (h < 65) {
        float pon = 0, poff = 0, Sh = 0;
        #pragma unroll
        for (int cc = 0; cc < 4; cc++) {
            Sh += ssf[cc][h];
            if (cc < c) { pon += ssn[cc][h]; poff += ssf[cc][h]; }
        }
        int j0 = c * 128;
        float* ctxb = g_ctx + b * TT * 65;
        for (int j = j0; j < j0 + 128; j++) {
            float qv = qb[j * 65 + h];
            pon  = fmaf(eon[j],  qv, pon);
            poff = fmaf(eoff[j], qv, poff);
            ctxb[j * 65 + h] = (pon + Sh - poff) * invD[j];
        }
    }
}

// ---------------- Z = enc@oh^T + ctx@oz^T + biases -> packed fp16 ----------
__global__ void k_zmix(const float* __restrict__ oh_w, const float* __restrict__ oh_b,
                       const float* __restrict__ oz_w, const float* __restrict__ oz_b) {
    __shared__ float swh[65 * 65], swz[65 * 65];
    __shared__ float senc[16 * 65], sctx[16 * 65];
    __shared__ float sz[16 * 65];
    int row0 = blockIdx.x * 16, tid = threadIdx.x;
    for (int i = tid; i < 65 * 65; i += 256) { swh[i] = oh_w[i]; swz[i] = oz_w[i]; }
    for (int i = tid; i < 16 * 65; i += 256) { senc[i] = g_enc[row0 * 65 + i]; sctx[i] = g_ctx[row0 * 65 + i]; }
    __syncthreads();
    for (int o = tid; o < 16 * 65; o += 256) {
        int r = o / 65, j = o - r * 65;
        float acc = oh_b[j] + oz_b[j];
        const float* wh = swh + j * 65;
        const float* wz = swz + j * 65;
        const float* xe = senc + r * 65;
        const float* xc = sctx + r * 65;
        #pragma unroll 13
        for (int k = 0; k < 65; k++) {
            acc = fmaf(wh[k], xe[k], acc);
            acc = fmaf(wz[k], xc[k], acc);
        }
        sz[o] = acc;
    }
    __syncthreads();
    for (int o = tid; o < 16 * 72; o += 256) {
        int r = o / 72, p = o - r * 72, k0 = 2 * p;
        __half2 val;
        val.x = zb_elem(sz + r * 65, k0);
        val.y = zb_elem(sz + r * 65, k0 + 1);
        *(__half2*)(g_Zb + ((size_t)(row0 + r)) * KB16 + k0) = val;
    }
}

// ---------------- HMMA output GEMM (M-tile 64, 2 CTAs/SM, K=144) -----------
// exact round-11 configuration (best verified: 532.3us total)
#define SROWB 304                 /* smem row stride: 288 data + 16 pad */
#define BTILE_BYTES (128 * SROWB) /* 38912 */
#define ATILE_BYTES (64 * SROWB)  /* 19456 */
#define OFF_BIAS 0
#define OFF_B 512
#define OFF_A0 (512 + BTILE_BYTES)
#define OFF_A1 (512 + BTILE_BYTES + ATILE_BYTES)
#define GEMM_SMEM (512 + BTILE_BYTES + 2 * ATILE_BYTES)   /* 78336 */

__device__ __forceinline__ void fill_tile_async(uint32_t sbase, const char* src,
                                                int rows, int tid) {
    for (int c = tid; c < rows * 18; c += 256) {
        int r = c / 18, kc = c - r * 18;
        cp16(sbase + r * SROWB + kc * 16, src + r * 288 + kc * 16);
    }
}

__global__ void __launch_bounds__(256, 2) k_gemm(const float* __restrict__ ov_b,
                                                 float* __restrict__ out) {
    extern __shared__ __align__(16) char sm[];
    uint32_t sb = smem_u32(sm);
    int tid = threadIdx.x, wid = tid >> 5, lid = tid & 31;
    int warp_m = wid & 1, warp_n = wid >> 1;
    int v0 = blockIdx.x * 128;
    int rg = blockIdx.y;

    float* sbias = (float*)(sm + OFF_BIAS);
    if (tid < 128) sbias[tid] = ov_b[v0 + tid];

    fill_tile_async(sb + OFF_B, (const char*)(g_Wb + (size_t)v0 * KB16), 128, tid);
    fill_tile_async(sb + OFF_A0, (const char*)(g_Zb + (size_t)(rg * 512) * KB16), 64, tid);
    CP_COMMIT();
    CP_WAIT0();
    __syncthreads();

    uint32_t pA = (uint32_t)((warp_m * 32 + (lid & 15)) * SROWB + (lid >> 4) * 16);
    uint32_t pB = (uint32_t)((warp_n * 32 + (lid & 7) + ((lid >> 4) & 1) * 8) * SROWB
                             + ((lid >> 3) & 1) * 16);
    uint32_t bAddr = sb + OFF_B + pB;

    for (int i = 0; i < 8; i++) {
        int row0 = rg * 512 + i * 64;
        if (i < 7) {
            fill_tile_async(sb + ((i & 1) ? OFF_A0 : OFF_A1),
                            (const char*)(g_Zb + (size_t)(row0 + 64) * KB16), 64, tid);
            CP_COMMIT();
        }

        uint32_t aAddr = sb + ((i & 1) ? OFF_A1 : OFF_A0) + pA;
        float c[8][4];
        #pragma unroll
        for (int f = 0; f < 8; f++) { c[f][0] = c[f][1] = c[f][2] = c[f][3] = 0.f; }

        #pragma unroll
        for (int kk = 0; kk < 9; kk++) {
            uint32_t a[2][4];
            #pragma unroll
            for (int mf = 0; mf < 2; mf++)
                LDSM4(a[mf][0], a[mf][1], a[mf][2], a[mf][3],
                      aAddr + mf * (16 * SROWB) + kk * 32);
            uint32_t bq[2][4];
            #pragma unroll
            for (int n2 = 0; n2 < 2; n2++)
                LDSM4(bq[n2][0], bq[n2][1], bq[n2][2], bq[n2][3],
                      bAddr + n2 * (16 * SROWB) + kk * 32);
            #pragma unroll
            for (int mf = 0; mf < 2; mf++) {
                #pragma unroll
                for (int nf = 0; nf < 4; nf++)
                    mma16816(c[mf * 4 + nf], a[mf],
                             bq[nf >> 1][(nf & 1) * 2], bq[nf >> 1][(nf & 1) * 2 + 1]);
            }
        }

        int rbase = row0 + warp_m * 32 + (lid >> 2);
        int cloc  = warp_n * 32 + (lid & 3) * 2;
        #pragma unroll
        for (int mf = 0; mf < 2; mf++) {
            #pragma unroll
            for (int nf = 0; nf < 4; nf++) {
                float* cc = c[mf * 4 + nf];
                int col = cloc + nf * 8;
                float b0 = sbias[col], b1 = sbias[col + 1];
                size_t o1 = (size_t)(rbase + mf * 16) * VV + v0 + col;
                size_t o2 = (size_t)(rbase + mf * 16 + 8) * VV + v0 + col;
                *(float2*)(out + o1) = make_float2(cc[0] + b0, cc[1] + b1);
                *(float2*)(out + o2) = make_float2(cc[2] + b0, cc[3] + b1);
            }
        }

        if (i < 7) {
            CP_WAIT0();
            __syncthreads();
        }
    }
}

// ---------------------------------------------------------------------------
extern "C" void kernel_launch(void* const* d_in, const int* in_sizes, int n_in,
                              void* d_out, int out_size) {
    const int*   ids  = (const int*)  d_in[0];
    const float* h0   = (const float*)d_in[1];
    const float* c0   = (const float*)d_in[2];
    const float* emb  = (const float*)d_in[3];
    const float* w_ih = (const float*)d_in[4];
    const float* w_hh = (const float*)d_in[5];
    const float* b_ih = (const float*)d_in[6];
    const float* b_hh = (const float*)d_in[7];
    const float* u_w  = (const float*)d_in[8];
    const float* u_b  = (const float*)d_in[9];
    const float* w_w  = (const float*)d_in[10];
    const float* w_b  = (const float*)d_in[11];
    const float* v_w  = (const float*)d_in[12];
    const float* v_b  = (const float*)d_in[13];
    const float* oz_w = (const float*)d_in[14];
    const float* oz_b = (const float*)d_in[15];
    const float* oh_w = (const float*)d_in[16];
    const float* oh_b = (const float*)d_in[17];
    const float* ov_w = (const float*)d_in[18];
    const float* ov_b = (const float*)d_in[19];

    float* out  = (float*)d_out;
    float* outH = out + OUT_MAIN_SIZE;
    float* outC = outH + BB * HH;

    static int smem_set = 0;
    if (!smem_set) {
        cudaFuncSetAttribute(k_gemm, cudaFuncAttributeMaxDynamicSharedMemorySize, GEMM_SMEM);
        smem_set = 1;
    }

    k_embed<<<dim3(NROW / 16, 2), 256>>>(ids, emb, w_ih, b_ih, b_hh);    // 1
    k_lstm_pack<<<BB + VV / 64, 1024>>>(h0, c0, w_hh, ov_w, outH, outC); // 2
    k_keys<<<NROW / 16, 256>>>(u_w, u_b, w_w, w_b, v_w, v_b);            // 3
    k_attn<<<BB, 288>>>();                                               // 4 (profiled)
    k_zmix<<<NROW / 16, 256>>>(oh_w, oh_b, oz_w, oz_b);                  // 5
    k_gemm<<<dim3(VV / 128, 8), 256, GEMM_SMEM>>>(ov_b, out);            // 6
}

// round 16
// speedup vs baseline: 1.4467x; 1.4467x over previous
#include <cuda_runtime.h>
#include <cuda_fp16.h>
#include <cstdint>

#define BB 8
#define TT 512
#define HH 65
#define G4 260
#define VV 32000
#define NROW (BB*TT)          /* 4096 */
#define KB16 144              /* packed fp16 K per row: [Zhi(68)|Zlo(68)|0(8)] */

static const long long OUT_MAIN_SIZE = (long long)NROW * VV;  // 131072000

// ---------------- scratch (device globals; no allocation allowed) ----------
__device__ float g_Xg[NROW * G4];
__device__ float g_enc[NROW * HH];
__device__ float g_q[NROW * HH];
__device__ float g_son[NROW];
__device__ float g_soff[NROW];
__device__ float g_ctx[NROW * HH];
__device__ __half g_Zb[NROW * KB16];          // packed A rows (fp16)
__device__ __half g_Wb[(size_t)VV * KB16];    // packed B rows (fp16)

// ---------------- small helpers -------------------------------------------
union F2U { float2 f; unsigned long long u; };
__device__ __forceinline__ unsigned long long ffma2u(unsigned long long a,
                                                     unsigned long long b,
                                                     unsigned long long c) {
    unsigned long long d;
    asm("fma.rn.f32x2 %0, %1, %2, %3;" : "=l"(d) : "l"(a), "l"(b), "l"(c));
    return d;
}
__device__ __forceinline__ unsigned long long addx2(unsigned long long a,
                                                    unsigned long long b) {
    unsigned long long d;
    asm("add.rn.f32x2 %0, %1, %2;" : "=l"(d) : "l"(a), "l"(b));
    return d;
}
__device__ __forceinline__ float tanh_fast(float x) {
    return 1.f - __fdividef(2.f, __expf(2.f * x) + 1.f);
}
__device__ __forceinline__ uint32_t smem_u32(const void* p) {
    uint32_t a;
    asm("{ .reg .u64 t; cvta.to.shared.u64 t, %1; cvt.u32.u64 %0, t; }" : "=r"(a) : "l"(p));
    return a;
}

// fp16 2-section packers. A: [Zhi(68)|Zlo(68)|0(8)]  B: [Whi(68)|Whi(68)|0(8)]
__device__ __forceinline__ __half zb_elem(const float* zr, int k) {
    int j = (k < 68) ? k : k - 68;
    if (k >= 136 || j >= 65) return __float2half(0.f);
    float z = zr[j];
    __half hi = __float2half(z);
    if (k >= 68) return __float2half(z - __half2float(hi));
    return hi;
}
__device__ __forceinline__ __half wb_elem(const float* wr, int k) {
    int j = (k < 68) ? k : k - 68;
    if (k >= 136 || j >= 65) return __float2half(0.f);
    return __float2half(wr[j]);
}

// ---------------- warp MMA primitives (baseline PTX, works at sm_103) ------
#define LDSM4(r0, r1, r2, r3, a) \
    asm volatile("ldmatrix.sync.aligned.m8n8.x4.shared.b16 {%0,%1,%2,%3}, [%4];" \
                 : "=r"(r0), "=r"(r1), "=r"(r2), "=r"(r3) : "r"(a))

__device__ __forceinline__ void mma16816(float* c, const uint32_t* a, uint32_t b0, uint32_t b1) {
    asm volatile(
        "mma.sync.aligned.m16n8k16.row.col.f32.f16.f16.f32 "
        "{%0,%1,%2,%3},{%4,%5,%6,%7},{%8,%9},{%0,%1,%2,%3};"
        : "+f"(c[0]), "+f"(c[1]), "+f"(c[2]), "+f"(c[3])
        : "r"(a[0]), "r"(a[1]), "r"(a[2]), "r"(a[3]), "r"(b0), "r"(b1));
}
__device__ __forceinline__ void cp16(uint32_t s, const void* g) {
    asm volatile("cp.async.cg.shared.global [%0], [%1], 16;" :: "r"(s), "l"(g));
}
#define CP_COMMIT() asm volatile("cp.async.commit_group;" ::: "memory")
#define CP_WAIT0()  asm volatile("cp.async.wait_group 0;" ::: "memory")

// ---------------- embedding + x-part of LSTM gates -------------------------
__global__ void k_embed(const int* __restrict__ ids, const float* __restrict__ emb,
                        const float* __restrict__ w_ih, const float* __restrict__ b_ih,
                        const float* __restrict__ b_hh) {
    __shared__ float sw[130 * 65];
    __shared__ float er[16 * 65];
    __shared__ float bs[130];
    int row0 = blockIdx.x * 16;
    int g0   = blockIdx.y * 130;
    int tid  = threadIdx.x;
    for (int i = tid; i < 130 * 65; i += 256) sw[i] = w_ih[g0 * 65 + i];
    for (int i = tid; i < 16 * 65; i += 256) {
        int r = i / 65, k = i - r * 65;
        er[i] = emb[ids[row0 + r] * 65 + k];
    }
    if (tid < 130) bs[tid] = b_ih[g0 + tid] + b_hh[g0 + tid];
    __syncthreads();
    for (int o = tid; o < 16 * 130; o += 256) {
        int r = o / 130, g = o - r * 130;
        float acc = bs[g];
        const float* w = sw + g * 65;
        const float* x = er + r * 65;
        #pragma unroll 13
        for (int k = 0; k < 65; k++) acc = fmaf(w[k], x[k], acc);
        g_Xg[(row0 + r) * G4 + g0 + g] = acc;
    }
}

// ---------------- fused LSTM recurrence + weight pack (round-11 exact) -----
__global__ void __launch_bounds__(544, 1)
k_lstm_pack(const float* __restrict__ h0, const float* __restrict__ c0,
            const float* __restrict__ w_hh, const float* __restrict__ ov_w,
            float* __restrict__ outH, float* __restrict__ outC) {
    int tid = threadIdx.x;

    if (blockIdx.x >= BB) {
        int v0 = (blockIdx.x - BB) * 64;
        for (int o = tid; o < 64 * 72; o += 544) {
            int r = o / 72, p = o - r * 72, k0 = 2 * p;
            const float* wr = ov_w + (size_t)(v0 + r) * 65;
            __half2 val;
            val.x = wb_elem(wr, k0);
            val.y = wb_elem(wr, k0 + 1);
            *(__half2*)(g_Wb + ((size_t)(v0 + r)) * KB16 + k0) = val;
        }
        return;
    }

    int b = blockIdx.x;
    int w = tid >> 5, lane = tid & 31;
    int jl   = lane >> 3;            // 0..3
    int gate = (lane >> 1) & 3;      // 0:i 1:f 2:g 3:o
    int half = lane & 1;
    int j  = (w << 2) + jl;          // 0..67
    int jc = (j < 65) ? j : 64;
    int rowc = gate * 65 + jc;
    bool upd = (j < 65) && (gate == 0) && (half == 0);

    __shared__ __align__(16) float hs[2][68];

    const float* wr = w_hh + rowc * 65 + half * 32;
    F2U w2[17];
    #pragma unroll
    for (int i = 0; i < 16; i++) { w2[i].f.x = wr[2 * i]; w2[i].f.y = wr[2 * i + 1]; }
    if (half) { w2[16].f.x = w_hh[rowc * 65 + 64]; w2[16].f.y = 0.f; }
    else      { w2[16].f.x = 0.f;                  w2[16].f.y = 0.f; }

    float c1   = (gate == 2) ? -2.885390082f : -1.442695041f;
    float amul = (gate == 2) ? 2.f : 1.f;
    float aadd = (gate == 2) ? -1.f : 0.f;

    float c = upd ? c0[b * 65 + j] : 0.f;
    if (tid < 65) hs[0][tid] = h0[b * 65 + tid];
    if (tid >= 65 && tid < 68) { hs[0][tid] = 0.f; hs[1][tid] = 0.f; }

    const float* xgp = g_Xg + (size_t)b * TT * G4 + rowc;
    float xg_cur = half ? 0.f : xgp[0];
    __syncthreads();

    for (int t = 0; t < TT; t++) {
        float xg_next = 0.f;
        if (!half && t + 1 < TT) xg_next = xgp[(size_t)(t + 1) * G4];

        const ulonglong2* h4 = (const ulonglong2*)hs[t & 1] + half * 8;
        F2U a0, a1, a2, a3;
        a0.f = make_float2(xg_cur, 0.f);
        a1.u = 0ull; a2.u = 0ull; a3.u = 0ull;
        #pragma unroll
        for (int i = 0; i < 4; i++) {
            ulonglong2 q0 = h4[2 * i];
            ulonglong2 q1 = h4[2 * i + 1];
            a0.u = ffma2u(w2[4 * i].u,     q0.x, a0.u);
            a1.u = ffma2u(w2[4 * i + 1].u, q0.y, a1.u);
            a2.u = ffma2u(w2[4 * i + 2].u, q1.x, a2.u);
            a3.u = ffma2u(w2[4 * i + 3].u, q1.y, a3.u);
        }
        if (half) {
            unsigned long long h64 = *(const unsigned long long*)(hs[t & 1] + 64);
            a0.u = ffma2u(w2[16].u, h64, a0.u);
        }
        F2U s;
        s.u = addx2(addx2(a0.u, a1.u), addx2(a2.u, a3.u));
        float part = s.f.x + s.f.y;
        float sum = part + __shfl_xor_sync(0xffffffffu, part, 1);

        float ex;
        asm("ex2.approx.f32 %0, %1;" : "=f"(ex) : "f"(c1 * sum));
        float sg = __fdividef(1.f, 1.f + ex);
        float av = fmaf(amul, sg, aadd);

        int base = lane & ~7;
        float fv = __shfl_sync(0xffffffffu, av, base + 2);
        float gg = __shfl_sync(0xffffffffu, av, base + 4);
        float ov = __shfl_sync(0xffffffffu, av, base + 6);

        if (upd) {
            c = fv * c + av * gg;
            float h = ov * tanh_fast(c);
            hs[(t + 1) & 1][j] = h;
            g_enc[(size_t)(b * TT + t) * HH + j] = h;
        }
        __syncthreads();
        xg_cur = xg_next;
    }
    if (upd) { outH[b * 65 + j] = hs[TT & 1][j]; outC[b * 65 + j] = c; }
}

// ---------------- queries + attention scores (8 rows/block, grid 512) ------
__global__ void k_keys(const float* __restrict__ u_w, const float* __restrict__ u_b,
                       const float* __restrict__ w_w, const float* __restrict__ w_b,
                       const float* __restrict__ v_w, const float* __restrict__ v_b) {
    __shared__ float swu[65 * 65];
    __shared__ float sww[65 * 65];
    __shared__ float senc[8 * 65];
    __shared__ float sq[8 * 65];
    __shared__ float skq[8 * 65];
    __shared__ float sv[65];
    int row0 = blockIdx.x * 8, tid = threadIdx.x;
    for (int i = tid; i < 65 * 65; i += 256) { swu[i] = u_w[i]; sww[i] = w_w[i]; }
    for (int i = tid; i < 8 * 65; i += 256) senc[i] = g_enc[row0 * 65 + i];
    if (tid < 65) sv[tid] = v_w[tid];
    __syncthreads();
    for (int o = tid; o < 8 * 65; o += 256) {
        int r = o / 65, j = o - r * 65;
        float aq = u_b[j], ak = w_b[j];
        const float* wu = swu + j * 65;
        const float* wk = sww + j * 65;
        const float* x  = senc + r * 65;
        #pragma unroll 13
        for (int k = 0; k < 65; k++) {
            aq = fmaf(wu[k], x[k], aq);
            ak = fmaf(wk[k], x[k], ak);
        }
        sq[o] = aq;
        skq[o] = ak;
        g_q[(row0 + r) * 65 + j] = aq;
    }
    __syncthreads();
    int r = tid >> 5, l = tid & 31;   // 32 lanes per row
    float sn = 0.f, sf = 0.f;
    for (int j = l; j < 65; j += 32) {
        float kq = skq[r * 65 + j];
        float qv = sq[r * 65 + j];
        float vj = sv[j];
        sn = fmaf(vj, tanh_fast(kq + qv), sn);
        sf = fmaf(vj, tanh_fast(kq), sf);
    }
    #pragma unroll
    for (int off = 16; off; off >>= 1) {
        sn += __shfl_down_sync(0xffffffffu, sn, off);
        sf += __shfl_down_sync(0xffffffffu, sf, off);
    }
    if (l == 0) {
        g_son[row0 + r]  = sn + v_b[0];
        g_soff[row0 + r] = sf + v_b[0];
    }
}

// ---------------- attention via prefix sums (576 thr: 8 chunks x 64 j) -----
__global__ void __launch_bounds__(576, 1) k_attn() {
    int b = blockIdx.x, tid = threadIdx.x;
    __shared__ float eon[512], eoff[512], con[512], coff[512], invD[512];
    __shared__ float ssn[8][72], ssf[8][72];
    __shared__ float offon[16], offoff[16];
    __shared__ float red[576];
    __shared__ float Msh, totoff_sh;
    const float* son  = g_son  + b * TT;
    const float* soff = g_soff + b * TT;

    float m = -1e30f;
    for (int j = tid; j < TT; j += 576) m = fmaxf(m, fmaxf(son[j], soff[j]));
    red[tid] = m;
    __syncthreads();
    if (tid == 0) { float mm = red[0]; for (int i = 1; i < 576; i++) mm = fmaxf(mm, red[i]); Msh = mm; }
    __syncthreads();
    float M = Msh;
    for (int j = tid; j < TT; j += 576) { eon[j] = __expf(son[j] - M); eoff[j] = __expf(soff[j] - M); }
    __syncthreads();
    if (tid < 16) {
        float s = 0; int base = tid * 32;
        for (int k = 0; k < 32; k++) { s += eon[base + k]; con[base + k] = s; }
    } else if (tid < 32) {
        float s = 0; int base = (tid - 16) * 32;
        for (int k = 0; k < 32; k++) { s += eoff[base + k]; coff[base + k] = s; }
    }
    __syncthreads();
    if (tid == 0) { float s = 0; for (int c = 0; c < 16; c++) { offon[c] = s;  s += con[c * 32 + 31]; } }
    if (tid == 1) { float s = 0; for (int c = 0; c < 16; c++) { offoff[c] = s; s += coff[c * 32 + 31]; } }
    __syncthreads();
    for (int j = tid; j < TT; j += 576) { con[j] += offon[j >> 5]; coff[j] += offoff[j >> 5]; }
    __syncthreads();
    if (tid == 0) totoff_sh = coff[511];
    __syncthreads();
    float totoff = totoff_sh;
    for (int i = tid; i < TT; i += 576) invD[i] = 1.f / (con[i] + totoff - coff[i]);
    __syncthreads();

    int c = tid / 72, h = tid - c * 72;   // 8 chunks x 72 (65 active) = 576
    const float* qb = g_q + b * TT * 65;
    if (h < 65) {
        int j0 = c * 64;
        float sn = 0, sf = 0;
        for (int j = j0; j < j0 + 64; j++) {
            float qv = qb[j * 65 + h];
            sn = fmaf(eon[j], qv, sn);
            sf = fmaf(eoff[j], qv, sf);
        }
        ssn[c][h] = sn; ssf[c][h] = sf;
    }
    __syncthreads();
    if (h < 65) {
        float pon = 0, poff = 0, Sh = 0;
        #pragma unroll
        for (int cc = 0; cc < 8; cc++) {
            Sh += ssf[cc][h];
            if (cc < c) { pon += ssn[cc][h]; poff += ssf[cc][h]; }
        }
        int j0 = c * 64;
        float* ctxb = g_ctx + b * TT * 65;
        for (int j = j0; j < j0 + 64; j++) {
            float qv = qb[j * 65 + h];
            pon  = fmaf(eon[j],  qv, pon);
            poff = fmaf(eoff[j], qv, poff);
            ctxb[j * 65 + h] = (pon + Sh - poff) * invD[j];
        }
    }
}

// ---------------- Z = enc@oh^T + ctx@oz^T + biases -> packed fp16 ----------
__global__ void k_zmix(const float* __restrict__ oh_w, const float* __restrict__ oh_b,
                       const float* __restrict__ oz_w, const float* __restrict__ oz_b) {
    __shared__ float swh[65 * 65], swz[65 * 65];
    __shared__ float senc[16 * 65], sctx[16 * 65];
    __shared__ float sz[16 * 65];
    int row0 = blockIdx.x * 16, tid = threadIdx.x;
    for (int i = tid; i < 65 * 65; i += 256) { swh[i] = oh_w[i]; swz[i] = oz_w[i]; }
    for (int i = tid; i < 16 * 65; i += 256) { senc[i] = g_enc[row0 * 65 + i]; sctx[i] = g_ctx[row0 * 65 + i]; }
    __syncthreads();
    for (int o = tid; o < 16 * 65; o += 256) {
        int r = o / 65, j = o - r * 65;
        float acc = oh_b[j] + oz_b[j];
        const float* wh = swh + j * 65;
        const float* wz = swz + j * 65;
        const float* xe = senc + r * 65;
        const float* xc = sctx + r * 65;
        #pragma unroll 13
        for (int k = 0; k < 65; k++) {
            acc = fmaf(wh[k], xe[k], acc);
            acc = fmaf(wz[k], xc[k], acc);
        }
        sz[o] = acc;
    }
    __syncthreads();
    for (int o = tid; o < 16 * 72; o += 256) {
        int r = o / 72, p = o - r * 72, k0 = 2 * p;
        __half2 val;
        val.x = zb_elem(sz + r * 65, k0);
        val.y = zb_elem(sz + r * 65, k0 + 1);
        *(__half2*)(g_Zb + ((size_t)(row0 + r)) * KB16 + k0) = val;
    }
}

// ---------------- HMMA output GEMM (M-tile 64, 2 CTAs/SM, K=144) -----------
// exact round-11 configuration
#define SROWB 304                 /* smem row stride: 288 data + 16 pad */
#define BTILE_BYTES (128 * SROWB) /* 38912 */
#define ATILE_BYTES (64 * SROWB)  /* 19456 */
#define OFF_BIAS 0
#define OFF_B 512
#define OFF_A0 (512 + BTILE_BYTES)
#define OFF_A1 (512 + BTILE_BYTES + ATILE_BYTES)
#define GEMM_SMEM (512 + BTILE_BYTES + 2 * ATILE_BYTES)   /* 78336 */

__device__ __forceinline__ void fill_tile_async(uint32_t sbase, const char* src,
                                                int rows, int tid) {
    for (int c = tid; c < rows * 18; c += 256) {
        int r = c / 18, kc = c - r * 18;
        cp16(sbase + r * SROWB + kc * 16, src + r * 288 + kc * 16);
    }
}

__global__ void __launch_bounds__(256, 2) k_gemm(const float* __restrict__ ov_b,
                                                 float* __restrict__ out) {
    extern __shared__ __align__(16) char sm[];
    uint32_t sb = smem_u32(sm);
    int tid = threadIdx.x, wid = tid >> 5, lid = tid & 31;
    int warp_m = wid & 1, warp_n = wid >> 1;
    int v0 = blockIdx.x * 128;
    int rg = blockIdx.y;

    float* sbias = (float*)(sm + OFF_BIAS);
    if (tid < 128) sbias[tid] = ov_b[v0 + tid];

    fill_tile_async(sb + OFF_B, (const char*)(g_Wb + (size_t)v0 * KB16), 128, tid);
    fill_tile_async(sb + OFF_A0, (const char*)(g_Zb + (size_t)(rg * 512) * KB16), 64, tid);
    CP_COMMIT();
    CP_WAIT0();
    __syncthreads();

    uint32_t pA = (uint32_t)((warp_m * 32 + (lid & 15)) * SROWB + (lid >> 4) * 16);
    uint32_t pB = (uint32_t)((warp_n * 32 + (lid & 7) + ((lid >> 4) & 1) * 8) * SROWB
                             + ((lid >> 3) & 1) * 16);
    uint32_t bAddr = sb + OFF_B + pB;

    for (int i = 0; i < 8; i++) {
        int row0 = rg * 512 + i * 64;
        if (i < 7) {
            fill_tile_async(sb + ((i & 1) ? OFF_A0 : OFF_A1),
                            (const char*)(g_Zb + (size_t)(row0 + 64) * KB16), 64, tid);
            CP_COMMIT();
        }

        uint32_t aAddr = sb + ((i & 1) ? OFF_A1 : OFF_A0) + pA;
        float c[8][4];
        #pragma unroll
        for (int f = 0; f < 8; f++) { c[f][0] = c[f][1] = c[f][2] = c[f][3] = 0.f; }

        #pragma unroll
        for (int kk = 0; kk < 9; kk++) {
            uint32_t a[2][4];
            #pragma unroll
            for (int mf = 0; mf < 2; mf++)
                LDSM4(a[mf][0], a[mf][1], a[mf][2], a[mf][3],
                      aAddr + mf * (16 * SROWB) + kk * 32);
            uint32_t bq[2][4];
            #pragma unroll
            for (int n2 = 0; n2 < 2; n2++)
                LDSM4(bq[n2][0], bq[n2][1], bq[n2][2], bq[n2][3],
                      bAddr + n2 * (16 * SROWB) + kk * 32);
            #pragma unroll
            for (int mf = 0; mf < 2; mf++) {
                #pragma unroll
                for (int nf = 0; nf < 4; nf++)
                    mma16816(c[mf * 4 + nf], a[mf],
                             bq[nf >> 1][(nf & 1) * 2], bq[nf >> 1][(nf & 1) * 2 + 1]);
            }
        }

        int rbase = row0 + warp_m * 32 + (lid >> 2);
        int cloc  = warp_n * 32 + (lid & 3) * 2;
        #pragma unroll
        for (int mf = 0; mf < 2; mf++) {
            #pragma unroll
            for (int nf = 0; nf < 4; nf++) {
                float* cc = c[mf * 4 + nf];
                int col = cloc + nf * 8;
                float b0 = sbias[col], b1 = sbias[col + 1];
                size_t o1 = (size_t)(rbase + mf * 16) * VV + v0 + col;
                size_t o2 = (size_t)(rbase + mf * 16 + 8) * VV + v0 + col;
                *(float2*)(out + o1) = make_float2(cc[0] + b0, cc[1] + b1);
                *(float2*)(out + o2) = make_float2(cc[2] + b0, cc[3] + b1);
            }
        }

        if (i < 7) {
            CP_WAIT0();
            __syncthreads();
        }
    }
}

// ---------------------------------------------------------------------------
extern "C" void kernel_launch(void* const* d_in, const int* in_sizes, int n_in,
                              void* d_out, int out_size) {
    const int*   ids  = (const int*)  d_in[0];
    const float* h0   = (const float*)d_in[1];
    const float* c0   = (const float*)d_in[2];
    const float* emb  = (const float*)d_in[3];
    const float* w_ih = (const float*)d_in[4];
    const float* w_hh = (const float*)d_in[5];
    const float* b_ih = (const float*)d_in[6];
    const float* b_hh = (const float*)d_in[7];
    const float* u_w  = (const float*)d_in[8];
    const float* u_b  = (const float*)d_in[9];
    const float* w_w  = (const float*)d_in[10];
    const float* w_b  = (const float*)d_in[11];
    const float* v_w  = (const float*)d_in[12];
    const float* v_b  = (const float*)d_in[13];
    const float* oz_w = (const float*)d_in[14];
    const float* oz_b = (const float*)d_in[15];
    const float* oh_w = (const float*)d_in[16];
    const float* oh_b = (const float*)d_in[17];
    const float* ov_w = (const float*)d_in[18];
    const float* ov_b = (const float*)d_in[19];

    float* out  = (float*)d_out;
    float* outH = out + OUT_MAIN_SIZE;
    float* outC = outH + BB * HH;

    static int smem_set = 0;
    if (!smem_set) {
        cudaFuncSetAttribute(k_gemm, cudaFuncAttributeMaxDynamicSharedMemorySize, GEMM_SMEM);
        smem_set = 1;
    }

    k_embed<<<dim3(NROW / 16, 2), 256>>>(ids, emb, w_ih, b_ih, b_hh);   // 1
    k_lstm_pack<<<BB + VV / 64, 544>>>(h0, c0, w_hh, ov_w, outH, outC); // 2
    k_keys<<<NROW / 8, 256>>>(u_w, u_b, w_w, w_b, v_w, v_b);            // 3
    k_attn<<<BB, 576>>>();                                              // 4 (profiled)
    k_zmix<<<NROW / 16, 256>>>(oh_w, oh_b, oz_w, oz_b);                 // 5
    k_gemm<<<dim3(VV / 128, 8), 256, GEMM_SMEM>>>(ov_b, out);           // 6
}

// round 17
// speedup vs baseline: 1.4948x; 1.0332x over previous
#include <cuda_runtime.h>
#include <cuda_fp16.h>
#include <cstdint>

#define BB 8
#define TT 512
#define HH 65
#define G4 260
#define VV 32000
#define NROW (BB*TT)          /* 4096 */
#define KB16 144              /* packed fp16 K per row: [Zhi(68)|Zlo(68)|0(8)] */

static const long long OUT_MAIN_SIZE = (long long)NROW * VV;  // 131072000

// ---------------- scratch (device globals; no allocation allowed) ----------
__device__ float g_Xg[NROW * G4];
__device__ float g_enc[NROW * HH];
__device__ float g_q[NROW * HH];
__device__ float g_son[NROW];
__device__ float g_soff[NROW];
__device__ float g_ctx[NROW * HH];
__device__ __half g_Zb[NROW * KB16];          // packed A rows (fp16)
__device__ __half g_Wb[(size_t)VV * KB16];    // packed B rows (fp16)

// ---------------- small helpers -------------------------------------------
union F2U { float2 f; unsigned long long u; };
__device__ __forceinline__ unsigned long long ffma2u(unsigned long long a,
                                                     unsigned long long b,
                                                     unsigned long long c) {
    unsigned long long d;
    asm("fma.rn.f32x2 %0, %1, %2, %3;" : "=l"(d) : "l"(a), "l"(b), "l"(c));
    return d;
}
__device__ __forceinline__ unsigned long long addx2(unsigned long long a,
                                                    unsigned long long b) {
    unsigned long long d;
    asm("add.rn.f32x2 %0, %1, %2;" : "=l"(d) : "l"(a), "l"(b));
    return d;
}
__device__ __forceinline__ float tanh_fast(float x) {
    return 1.f - __fdividef(2.f, __expf(2.f * x) + 1.f);
}
__device__ __forceinline__ uint32_t smem_u32(const void* p) {
    uint32_t a;
    asm("{ .reg .u64 t; cvta.to.shared.u64 t, %1; cvt.u32.u64 %0, t; }" : "=r"(a) : "l"(p));
    return a;
}

// fp16 2-section packers. A: [Zhi(68)|Zlo(68)|0(8)]  B: [Whi(68)|Whi(68)|0(8)]
__device__ __forceinline__ __half zb_elem(const float* zr, int k) {
    int j = (k < 68) ? k : k - 68;
    if (k >= 136 || j >= 65) return __float2half(0.f);
    float z = zr[j];
    __half hi = __float2half(z);
    if (k >= 68) return __float2half(z - __half2float(hi));
    return hi;
}
__device__ __forceinline__ __half wb_elem(const float* wr, int k) {
    int j = (k < 68) ? k : k - 68;
    if (k >= 136 || j >= 65) return __float2half(0.f);
    return __float2half(wr[j]);
}

// ---------------- warp MMA primitives (baseline PTX, works at sm_103) ------
#define LDSM4(r0, r1, r2, r3, a) \
    asm volatile("ldmatrix.sync.aligned.m8n8.x4.shared.b16 {%0,%1,%2,%3}, [%4];" \
                 : "=r"(r0), "=r"(r1), "=r"(r2), "=r"(r3) : "r"(a))

__device__ __forceinline__ void mma16816(float* c, const uint32_t* a, uint32_t b0, uint32_t b1) {
    asm volatile(
        "mma.sync.aligned.m16n8k16.row.col.f32.f16.f16.f32 "
        "{%0,%1,%2,%3},{%4,%5,%6,%7},{%8,%9},{%0,%1,%2,%3};"
        : "+f"(c[0]), "+f"(c[1]), "+f"(c[2]), "+f"(c[3])
        : "r"(a[0]), "r"(a[1]), "r"(a[2]), "r"(a[3]), "r"(b0), "r"(b1));
}
__device__ __forceinline__ void cp16(uint32_t s, const void* g) {
    asm volatile("cp.async.cg.shared.global [%0], [%1], 16;" :: "r"(s), "l"(g));
}
#define CP_COMMIT() asm volatile("cp.async.commit_group;" ::: "memory")
#define CP_WAIT0()  asm volatile("cp.async.wait_group 0;" ::: "memory")

// ---------------- embedding + x-part of LSTM gates (8 rows/block) ----------
__global__ void k_embed(const int* __restrict__ ids, const float* __restrict__ emb,
                        const float* __restrict__ w_ih, const float* __restrict__ b_ih,
                        const float* __restrict__ b_hh) {
    __shared__ float sw[130 * 65];
    __shared__ float er[8 * 65];
    __shared__ float bs[130];
    int row0 = blockIdx.x * 8;
    int g0   = blockIdx.y * 130;
    int tid  = threadIdx.x;
    for (int i = tid; i < 130 * 65; i += 256) sw[i] = w_ih[g0 * 65 + i];
    for (int i = tid; i < 8 * 65; i += 256) {
        int r = i / 65, k = i - r * 65;
        er[i] = emb[ids[row0 + r] * 65 + k];
    }
    if (tid < 130) bs[tid] = b_ih[g0 + tid] + b_hh[g0 + tid];
    __syncthreads();
    for (int o = tid; o < 8 * 130; o += 256) {
        int r = o / 130, g = o - r * 130;
        float acc = bs[g];
        const float* w = sw + g * 65;
        const float* x = er + r * 65;
        #pragma unroll 13
        for (int k = 0; k < 65; k++) acc = fmaf(w[k], x[k], acc);
        g_Xg[(row0 + r) * G4 + g0 + g] = acc;
    }
}

// ---------------- fused LSTM recurrence + weight pack (round-11 exact) -----
__global__ void __launch_bounds__(544, 1)
k_lstm_pack(const float* __restrict__ h0, const float* __restrict__ c0,
            const float* __restrict__ w_hh, const float* __restrict__ ov_w,
            float* __restrict__ outH, float* __restrict__ outC) {
    int tid = threadIdx.x;

    if (blockIdx.x >= BB) {
        int v0 = (blockIdx.x - BB) * 64;
        for (int o = tid; o < 64 * 72; o += 544) {
            int r = o / 72, p = o - r * 72, k0 = 2 * p;
            const float* wr = ov_w + (size_t)(v0 + r) * 65;
            __half2 val;
            val.x = wb_elem(wr, k0);
            val.y = wb_elem(wr, k0 + 1);
            *(__half2*)(g_Wb + ((size_t)(v0 + r)) * KB16 + k0) = val;
        }
        return;
    }

    int b = blockIdx.x;
    int w = tid >> 5, lane = tid & 31;
    int jl   = lane >> 3;            // 0..3
    int gate = (lane >> 1) & 3;      // 0:i 1:f 2:g 3:o
    int half = lane & 1;
    int j  = (w << 2) + jl;          // 0..67
    int jc = (j < 65) ? j : 64;
    int rowc = gate * 65 + jc;
    bool upd = (j < 65) && (gate == 0) && (half == 0);

    __shared__ __align__(16) float hs[2][68];

    const float* wr = w_hh + rowc * 65 + half * 32;
    F2U w2[17];
    #pragma unroll
    for (int i = 0; i < 16; i++) { w2[i].f.x = wr[2 * i]; w2[i].f.y = wr[2 * i + 1]; }
    if (half) { w2[16].f.x = w_hh[rowc * 65 + 64]; w2[16].f.y = 0.f; }
    else      { w2[16].f.x = 0.f;                  w2[16].f.y = 0.f; }

    float c1   = (gate == 2) ? -2.885390082f : -1.442695041f;
    float amul = (gate == 2) ? 2.f : 1.f;
    float aadd = (gate == 2) ? -1.f : 0.f;

    float c = upd ? c0[b * 65 + j] : 0.f;
    if (tid < 65) hs[0][tid] = h0[b * 65 + tid];
    if (tid >= 65 && tid < 68) { hs[0][tid] = 0.f; hs[1][tid] = 0.f; }

    const float* xgp = g_Xg + (size_t)b * TT * G4 + rowc;
    float xg_cur = half ? 0.f : xgp[0];
    __syncthreads();

    for (int t = 0; t < TT; t++) {
        float xg_next = 0.f;
        if (!half && t + 1 < TT) xg_next = xgp[(size_t)(t + 1) * G4];

        const ulonglong2* h4 = (const ulonglong2*)hs[t & 1] + half * 8;
        F2U a0, a1, a2, a3;
        a0.f = make_float2(xg_cur, 0.f);
        a1.u = 0ull; a2.u = 0ull; a3.u = 0ull;
        #pragma unroll
        for (int i = 0; i < 4; i++) {
            ulonglong2 q0 = h4[2 * i];
            ulonglong2 q1 = h4[2 * i + 1];
            a0.u = ffma2u(w2[4 * i].u,     q0.x, a0.u);
            a1.u = ffma2u(w2[4 * i + 1].u, q0.y, a1.u);
            a2.u = ffma2u(w2[4 * i + 2].u, q1.x, a2.u);
            a3.u = ffma2u(w2[4 * i + 3].u, q1.y, a3.u);
        }
        if (half) {
            unsigned long long h64 = *(const unsigned long long*)(hs[t & 1] + 64);
            a0.u = ffma2u(w2[16].u, h64, a0.u);
        }
        F2U s;
        s.u = addx2(addx2(a0.u, a1.u), addx2(a2.u, a3.u));
        float part = s.f.x + s.f.y;
        float sum = part + __shfl_xor_sync(0xffffffffu, part, 1);

        float ex;
        asm("ex2.approx.f32 %0, %1;" : "=f"(ex) : "f"(c1 * sum));
        float sg = __fdividef(1.f, 1.f + ex);
        float av = fmaf(amul, sg, aadd);

        int base = lane & ~7;
        float fv = __shfl_sync(0xffffffffu, av, base + 2);
        float gg = __shfl_sync(0xffffffffu, av, base + 4);
        float ov = __shfl_sync(0xffffffffu, av, base + 6);

        if (upd) {
            c = fv * c + av * gg;
            float h = ov * tanh_fast(c);
            hs[(t + 1) & 1][j] = h;
            g_enc[(size_t)(b * TT + t) * HH + j] = h;
        }
        __syncthreads();
        xg_cur = xg_next;
    }
    if (upd) { outH[b * 65 + j] = hs[TT & 1][j]; outC[b * 65 + j] = c; }
}

// ---------------- queries + attention scores (8 rows/block, grid 512) ------
__global__ void k_keys(const float* __restrict__ u_w, const float* __restrict__ u_b,
                       const float* __restrict__ w_w, const float* __restrict__ w_b,
                       const float* __restrict__ v_w, const float* __restrict__ v_b) {
    __shared__ float swu[65 * 65];
    __shared__ float sww[65 * 65];
    __shared__ float senc[8 * 65];
    __shared__ float sq[8 * 65];
    __shared__ float skq[8 * 65];
    __shared__ float sv[65];
    int row0 = blockIdx.x * 8, tid = threadIdx.x;
    for (int i = tid; i < 65 * 65; i += 256) { swu[i] = u_w[i]; sww[i] = w_w[i]; }
    for (int i = tid; i < 8 * 65; i += 256) senc[i] = g_enc[row0 * 65 + i];
    if (tid < 65) sv[tid] = v_w[tid];
    __syncthreads();
    for (int o = tid; o < 8 * 65; o += 256) {
        int r = o / 65, j = o - r * 65;
        float aq = u_b[j], ak = w_b[j];
        const float* wu = swu + j * 65;
        const float* wk = sww + j * 65;
        const float* x  = senc + r * 65;
        #pragma unroll 13
        for (int k = 0; k < 65; k++) {
            aq = fmaf(wu[k], x[k], aq);
            ak = fmaf(wk[k], x[k], ak);
        }
        sq[o] = aq;
        skq[o] = ak;
        g_q[(row0 + r) * 65 + j] = aq;
    }
    __syncthreads();
    int r = tid >> 5, l = tid & 31;   // 32 lanes per row
    float sn = 0.f, sf = 0.f;
    for (int j = l; j < 65; j += 32) {
        float kq = skq[r * 65 + j];
        float qv = sq[r * 65 + j];
        float vj = sv[j];
        sn = fmaf(vj, tanh_fast(kq + qv), sn);
        sf = fmaf(vj, tanh_fast(kq), sf);
    }
    #pragma unroll
    for (int off = 16; off; off >>= 1) {
        sn += __shfl_down_sync(0xffffffffu, sn, off);
        sf += __shfl_down_sync(0xffffffffu, sf, off);
    }
    if (l == 0) {
        g_son[row0 + r]  = sn + v_b[0];
        g_soff[row0 + r] = sf + v_b[0];
    }
}

// ---------------- attention via prefix sums (576 thr: 8 chunks x 64 j) -----
__global__ void __launch_bounds__(576, 1) k_attn() {
    int b = blockIdx.x, tid = threadIdx.x;
    __shared__ float eon[512], eoff[512], con[512], coff[512], invD[512];
    __shared__ float ssn[8][72], ssf[8][72];
    __shared__ float offon[16], offoff[16];
    __shared__ float red[576];
    __shared__ float Msh, totoff_sh;
    const float* son  = g_son  + b * TT;
    const float* soff = g_soff + b * TT;

    float m = -1e30f;
    for (int j = tid; j < TT; j += 576) m = fmaxf(m, fmaxf(son[j], soff[j]));
    red[tid] = m;
    __syncthreads();
    if (tid == 0) { float mm = red[0]; for (int i = 1; i < 576; i++) mm = fmaxf(mm, red[i]); Msh = mm; }
    __syncthreads();
    float M = Msh;
    for (int j = tid; j < TT; j += 576) { eon[j] = __expf(son[j] - M); eoff[j] = __expf(soff[j] - M); }
    __syncthreads();
    if (tid < 16) {
        float s = 0; int base = tid * 32;
        for (int k = 0; k < 32; k++) { s += eon[base + k]; con[base + k] = s; }
    } else if (tid < 32) {
        float s = 0; int base = (tid - 16) * 32;
        for (int k = 0; k < 32; k++) { s += eoff[base + k]; coff[base + k] = s; }
    }
    __syncthreads();
    if (tid == 0) { float s = 0; for (int c = 0; c < 16; c++) { offon[c] = s;  s += con[c * 32 + 31]; } }
    if (tid == 1) { float s = 0; for (int c = 0; c < 16; c++) { offoff[c] = s; s += coff[c * 32 + 31]; } }
    __syncthreads();
    for (int j = tid; j < TT; j += 576) { con[j] += offon[j >> 5]; coff[j] += offoff[j >> 5]; }
    __syncthreads();
    if (tid == 0) totoff_sh = coff[511];
    __syncthreads();
    float totoff = totoff_sh;
    for (int i = tid; i < TT; i += 576) invD[i] = 1.f / (con[i] + totoff - coff[i]);
    __syncthreads();

    int c = tid / 72, h = tid - c * 72;   // 8 chunks x 72 (65 active) = 576
    const float* qb = g_q + b * TT * 65;
    if (h < 65) {
        int j0 = c * 64;
        float sn = 0, sf = 0;
        for (int j = j0; j < j0 + 64; j++) {
            float qv = qb[j * 65 + h];
            sn = fmaf(eon[j], qv, sn);
            sf = fmaf(eoff[j], qv, sf);
        }
        ssn[c][h] = sn; ssf[c][h] = sf;
    }
    __syncthreads();
    if (h < 65) {
        float pon = 0, poff = 0, Sh = 0;
        #pragma unroll
        for (int cc = 0; cc < 8; cc++) {
            Sh += ssf[cc][h];
            if (cc < c) { pon += ssn[cc][h]; poff += ssf[cc][h]; }
        }
        int j0 = c * 64;
        float* ctxb = g_ctx + b * TT * 65;
        for (int j = j0; j < j0 + 64; j++) {
            float qv = qb[j * 65 + h];
            pon  = fmaf(eon[j],  qv, pon);
            poff = fmaf(eoff[j], qv, poff);
            ctxb[j * 65 + h] = (pon + Sh - poff) * invD[j];
        }
    }
}

// ---------------- Z = enc@oh^T + ctx@oz^T + biases (8 rows/block) ----------
__global__ void k_zmix(const float* __restrict__ oh_w, const float* __restrict__ oh_b,
                       const float* __restrict__ oz_w, const float* __restrict__ oz_b) {
    __shared__ float swh[65 * 65], swz[65 * 65];
    __shared__ float senc[8 * 65], sctx[8 * 65];
    __shared__ float sz[8 * 65];
    int row0 = blockIdx.x * 8, tid = threadIdx.x;
    for (int i = tid; i < 65 * 65; i += 256) { swh[i] = oh_w[i]; swz[i] = oz_w[i]; }
    for (int i = tid; i < 8 * 65; i += 256) { senc[i] = g_enc[row0 * 65 + i]; sctx[i] = g_ctx[row0 * 65 + i]; }
    __syncthreads();
    for (int o = tid; o < 8 * 65; o += 256) {
        int r = o / 65, j = o - r * 65;
        float acc = oh_b[j] + oz_b[j];
        const float* wh = swh + j * 65;
        const float* wz = swz + j * 65;
        const float* xe = senc + r * 65;
        const float* xc = sctx + r * 65;
        #pragma unroll 13
        for (int k = 0; k < 65; k++) {
            acc = fmaf(wh[k], xe[k], acc);
            acc = fmaf(wz[k], xc[k], acc);
        }
        sz[o] = acc;
    }
    __syncthreads();
    for (int o = tid; o < 8 * 72; o += 256) {
        int r = o / 72, p = o - r * 72, k0 = 2 * p;
        __half2 val;
        val.x = zb_elem(sz + r * 65, k0);
        val.y = zb_elem(sz + r * 65, k0 + 1);
        *(__half2*)(g_Zb + ((size_t)(row0 + r)) * KB16 + k0) = val;
    }
}

// ---------------- HMMA output GEMM (M-tile 64, 2 CTAs/SM, K=144) -----------
#define SROWB 304                 /* smem row stride: 288 data + 16 pad */
#define BTILE_BYTES (128 * SROWB) /* 38912 */
#define ATILE_BYTES (64 * SROWB)  /* 19456 */
#define OFF_BIAS 0
#define OFF_B 512
#define OFF_A0 (512 + BTILE_BYTES)
#define OFF_A1 (512 + BTILE_BYTES + ATILE_BYTES)
#define GEMM_SMEM (512 + BTILE_BYTES + 2 * ATILE_BYTES)   /* 78336 */

__device__ __forceinline__ void fill_tile_async(uint32_t sbase, const char* src,
                                                int rows, int tid) {
    for (int c = tid; c < rows * 18; c += 256) {
        int r = c / 18, kc = c - r * 18;
        cp16(sbase + r * SROWB + kc * 16, src + r * 288 + kc * 16);
    }
}

__global__ void __launch_bounds__(256, 2) k_gemm(const float* __restrict__ ov_b,
                                                 float* __restrict__ out) {
    extern __shared__ __align__(16) char sm[];
    uint32_t sb = smem_u32(sm);
    int tid = threadIdx.x, wid = tid >> 5, lid = tid & 31;
    int warp_m = wid & 1, warp_n = wid >> 1;
    int v0 = blockIdx.x * 128;
    int rg = blockIdx.y;

    float* sbias = (float*)(sm + OFF_BIAS);
    if (tid < 128) sbias[tid] = ov_b[v0 + tid];

    fill_tile_async(sb + OFF_B, (const char*)(g_Wb + (size_t)v0 * KB16), 128, tid);
    fill_tile_async(sb + OFF_A0, (const char*)(g_Zb + (size_t)(rg * 512) * KB16), 64, tid);
    CP_COMMIT();
    CP_WAIT0();
    __syncthreads();

    uint32_t pA = (uint32_t)((warp_m * 32 + (lid & 15)) * SROWB + (lid >> 4) * 16);
    uint32_t pB = (uint32_t)((warp_n * 32 + (lid & 7) + ((lid >> 4) & 1) * 8) * SROWB
                             + ((lid >> 3) & 1) * 16);
    uint32_t bAddr = sb + OFF_B + pB;

    for (int i = 0; i < 8; i++) {
        int row0 = rg * 512 + i * 64;
        if (i < 7) {
            fill_tile_async(sb + ((i & 1) ? OFF_A0 : OFF_A1),
                            (const char*)(g_Zb + (size_t)(row0 + 64) * KB16), 64, tid);
            CP_COMMIT();
        }

        uint32_t aAddr = sb + ((i & 1) ? OFF_A1 : OFF_A0) + pA;
        float c[8][4];
        #pragma unroll
        for (int f = 0; f < 8; f++) { c[f][0] = c[f][1] = c[f][2] = c[f][3] = 0.f; }

        #pragma unroll
        for (int kk = 0; kk < 9; kk++) {
            uint32_t a[2][4];
            #pragma unroll
            for (int mf = 0; mf < 2; mf++)
                LDSM4(a[mf][0], a[mf][1], a[mf][2], a[mf][3],
                      aAddr + mf * (16 * SROWB) + kk * 32);
            uint32_t bq[2][4];
            #pragma unroll
            for (int n2 = 0; n2 < 2; n2++)
                LDSM4(bq[n2][0], bq[n2][1], bq[n2][2], bq[n2][3],
                      bAddr + n2 * (16 * SROWB) + kk * 32);
            #pragma unroll
            for (int mf = 0; mf < 2; mf++) {
                #pragma unroll
                for (int nf = 0; nf < 4; nf++)
                    mma16816(c[mf * 4 + nf], a[mf],
                             bq[nf >> 1][(nf & 1) * 2], bq[nf >> 1][(nf & 1) * 2 + 1]);
            }
        }

        int rbase = row0 + warp_m * 32 + (lid >> 2);
        int cloc  = warp_n * 32 + (lid & 3) * 2;
        #pragma unroll
        for (int mf = 0; mf < 2; mf++) {
            #pragma unroll
            for (int nf = 0; nf < 4; nf++) {
                float* cc = c[mf * 4 + nf];
                int col = cloc + nf * 8;
                float b0 = sbias[col], b1 = sbias[col + 1];
                size_t o1 = (size_t)(rbase + mf * 16) * VV + v0 + col;
                size_t o2 = (size_t)(rbase + mf * 16 + 8) * VV + v0 + col;
                __stcs((float2*)(out + o1), make_float2(cc[0] + b0, cc[1] + b1));
                __stcs((float2*)(out + o2), make_float2(cc[2] + b0, cc[3] + b1));
            }
        }

        if (i < 7) {
            CP_WAIT0();
            __syncthreads();
        }
    }
}

// ---------------------------------------------------------------------------
extern "C" void kernel_launch(void* const* d_in, const int* in_sizes, int n_in,
                              void* d_out, int out_size) {
    const int*   ids  = (const int*)  d_in[0];
    const float* h0   = (const float*)d_in[1];
    const float* c0   = (const float*)d_in[2];
    const float* emb  = (const float*)d_in[3];
    const float* w_ih = (const float*)d_in[4];
    const float* w_hh = (const float*)d_in[5];
    const float* b_ih = (const float*)d_in[6];
    const float* b_hh = (const float*)d_in[7];
    const float* u_w  = (const float*)d_in[8];
    const float* u_b  = (const float*)d_in[9];
    const float* w_w  = (const float*)d_in[10];
    const float* w_b  = (const float*)d_in[11];
    const float* v_w  = (const float*)d_in[12];
    const float* v_b  = (const float*)d_in[13];
    const float* oz_w = (const float*)d_in[14];
    const float* oz_b = (const float*)d_in[15];
    const float* oh_w = (const float*)d_in[16];
    const float* oh_b = (const float*)d_in[17];
    const float* ov_w = (const float*)d_in[18];
    const float* ov_b = (const float*)d_in[19];

    float* out  = (float*)d_out;
    float* outH = out + OUT_MAIN_SIZE;
    float* outC = outH + BB * HH;

    static int smem_set = 0;
    if (!smem_set) {
        cudaFuncSetAttribute(k_gemm, cudaFuncAttributeMaxDynamicSharedMemorySize, GEMM_SMEM);
        smem_set = 1;
    }

    k_embed<<<dim3(NROW / 8, 2), 256>>>(ids, emb, w_ih, b_ih, b_hh);    // 1
    k_lstm_pack<<<BB + VV / 64, 544>>>(h0, c0, w_hh, ov_w, outH, outC); // 2
    k_keys<<<NROW / 8, 256>>>(u_w, u_b, w_w, w_b, v_w, v_b);            // 3
    k_attn<<<BB, 576>>>();                                              // 4 (profiled)
    k_zmix<<<NROW / 8, 256>>>(oh_w, oh_b, oz_w, oz_b);                  // 5
    k_gemm<<<dim3(VV / 128, 8), 256, GEMM_SMEM>>>(ov_b, out);           // 6
}